// round 9
// baseline (speedup 1.0000x reference)
#include <cuda_runtime.h>

#define HIDDEN 2048
#define INTER  1408
#define TOPK   6
#define DK_ROWS 8   // h rows per down_partial block

// Scratch: intermediate activations (silu(gate)*up), 6*1408 floats = 33 KB.
__device__ float g_inter[TOPK * INTER];
// Scratch: weighted per-expert partial outputs, 6*2048 floats = 48 KB.
__device__ float g_partial[TOPK * HIDDEN];

__device__ __forceinline__ float dot4(float4 a, float4 b) {
    return a.x * b.x + a.y * b.y + a.z * b.z + a.w * b.w;
}

// ---------------------------------------------------------------------------
// Kernel 1: inter[k][i] = silu(gate_i . x) * (up_i . x)
// 256-thread block per (i-pair, expert). 10 float4 loads front-batched per
// thread -> ~6.4 TB/s measured. Unchanged (at the LTS ceiling).
// ---------------------------------------------------------------------------
__global__ void __launch_bounds__(256, 8)
gate_up_silu_kernel(const float* __restrict__ x,
                    const int* __restrict__ topk_idx,
                    const float* __restrict__ gu_all)
{
    const int i0 = blockIdx.x * 2;     // 0..1406 step 2
    const int k  = blockIdx.y;         // 0..5
    const int t  = threadIdx.x;

    const int e = topk_idx[k];
    const size_t base = ((size_t)e * (2 * INTER) + i0) * HIDDEN;

    const float4* __restrict__ xg  = (const float4*)x;
    const float4* __restrict__ g0p = (const float4*)(gu_all + base);
    const float4* __restrict__ g1p = (const float4*)(gu_all + base + HIDDEN);
    const float4* __restrict__ u0p = (const float4*)(gu_all + base + (size_t)INTER * HIDDEN);
    const float4* __restrict__ u1p = (const float4*)(gu_all + base + (size_t)INTER * HIDDEN + HIDDEN);

    float s0 = 0.f, s1 = 0.f, s2 = 0.f, s3 = 0.f;
    #pragma unroll
    for (int jj = 0; jj < 2; ++jj) {
        const int j = t + jj * 256;    // HIDDEN/4 = 512
        float4 xv = xg[j];
        float4 a  = g0p[j];
        float4 b  = g1p[j];
        float4 c  = u0p[j];
        float4 d  = u1p[j];
        s0 += dot4(xv, a);
        s1 += dot4(xv, b);
        s2 += dot4(xv, c);
        s3 += dot4(xv, d);
    }

    #pragma unroll
    for (int off = 16; off > 0; off >>= 1) {
        s0 += __shfl_down_sync(0xffffffff, s0, off);
        s1 += __shfl_down_sync(0xffffffff, s1, off);
        s2 += __shfl_down_sync(0xffffffff, s2, off);
        s3 += __shfl_down_sync(0xffffffff, s3, off);
    }

    __shared__ float sm[8][4];
    const int wid = t >> 5, lid = t & 31;
    if (lid == 0) { sm[wid][0] = s0; sm[wid][1] = s1; sm[wid][2] = s2; sm[wid][3] = s3; }
    __syncthreads();

    if (t == 0) {
        float G0 = 0.f, G1 = 0.f, U0 = 0.f, U1 = 0.f;
        #pragma unroll
        for (int w = 0; w < 8; ++w) {
            G0 += sm[w][0]; G1 += sm[w][1]; U0 += sm[w][2]; U1 += sm[w][3];
        }
        g_inter[k * INTER + i0]     = (G0 / (1.0f + expf(-G0))) * U0;
        g_inter[k * INTER + i0 + 1] = (G1 / (1.0f + expf(-G1))) * U1;
    }
}

// ---------------------------------------------------------------------------
// Kernel 2a: partial[k][h] = w[k] * dot(down[e_k][h][:], inter[k][:])
// Gate_up-shaped: 352 threads (= INTER/4 exactly), thread t owns column t:
//   1 L2 inter load + DK_ROWS=8 DRAM weight loads, all front-batched,
//   zero predication, zero tail. Grid 256 x 6 = 1536 blocks (~3.5 waves).
// ---------------------------------------------------------------------------
__global__ void __launch_bounds__(352)
down_partial_kernel(const int* __restrict__ topk_idx,
                    const float* __restrict__ topk_w,
                    const float* __restrict__ down_all)
{
    const int h0 = blockIdx.x * DK_ROWS;   // 0..2040 step 8
    const int k  = blockIdx.y;             // 0..5
    const int t  = threadIdx.x;            // 0..351 == float4 column index

    const int e = topk_idx[k];
    const float* base = down_all + ((size_t)e * HIDDEN + h0) * INTER;

    // Front-batched loads: 8 weight rows + 1 inter, all independent.
    float4 wv[DK_ROWS];
    #pragma unroll
    for (int r = 0; r < DK_ROWS; ++r)
        wv[r] = ((const float4*)(base + (size_t)r * INTER))[t];
    const float4 vv = ((const float4*)(g_inter + k * INTER))[t];

    float s[DK_ROWS];
    #pragma unroll
    for (int r = 0; r < DK_ROWS; ++r)
        s[r] = dot4(wv[r], vv);

    // Warp-level reduce each row sum.
    #pragma unroll
    for (int off = 16; off > 0; off >>= 1)
        #pragma unroll
        for (int r = 0; r < DK_ROWS; ++r)
            s[r] += __shfl_down_sync(0xffffffff, s[r], off);

    __shared__ float sm[11][DK_ROWS];      // 352 threads = 11 warps
    const int wid = t >> 5, lid = t & 31;
    if (lid == 0)
        #pragma unroll
        for (int r = 0; r < DK_ROWS; ++r)
            sm[wid][r] = s[r];
    __syncthreads();

    if (t < DK_ROWS) {
        float total = 0.f;
        #pragma unroll
        for (int w = 0; w < 11; ++w)
            total += sm[w][t];
        g_partial[k * HIDDEN + h0 + t] = topk_w[k] * total;
    }
}

// ---------------------------------------------------------------------------
// Kernel 2b: out[h] = sum_k partial[k][h]   (48 KB, L2-hot, trivial)
// ---------------------------------------------------------------------------
__global__ void __launch_bounds__(256)
combine_kernel(float* __restrict__ out)
{
    const int h = blockIdx.x * 256 + threadIdx.x;
    float s = 0.f;
    #pragma unroll
    for (int k = 0; k < TOPK; ++k)
        s += g_partial[k * HIDDEN + h];
    out[h] = s;
}

// ---------------------------------------------------------------------------
extern "C" void kernel_launch(void* const* d_in, const int* in_sizes, int n_in,
                              void* d_out, int out_size)
{
    const float* x        = (const float*)d_in[0];      // [1,2048,1,1]
    const int*   topk_idx = (const int*)d_in[1];        // [6] int32
    const float* topk_w   = (const float*)d_in[2];      // [6]
    const float* gu_all   = (const float*)d_in[3];      // [60, 2816, 2048]
    const float* down_all = (const float*)d_in[4];      // [60, 2048, 1408]
    float*       out      = (float*)d_out;              // [2048]

    dim3 grid1(INTER / 2, TOPK);
    gate_up_silu_kernel<<<grid1, 256>>>(x, topk_idx, gu_all);

    dim3 grid2(HIDDEN / DK_ROWS, TOPK);
    down_partial_kernel<<<grid2, 352>>>(topk_idx, topk_w, down_all);

    combine_kernel<<<HIDDEN / 256, 256>>>(out);
}